// round 15
// baseline (speedup 1.0000x reference)
#include <cuda_runtime.h>
#include <cuda_fp16.h>
#include <cstdint>
#include <cfloat>

#define GXD 480
#define GYD 360
#define NUM_VOX (GXD*GYD)
#define BATCH 2
#define NPTS 100000
#define MTOT (BATCH*NPTS)
#define NVB (BATCH*NUM_VOX)
#define BN_EPS 1e-5f
#define SCAN_BLOCKS 338
#define MTILES ((MTOT+127)/128)   /* 1563 */

// ---------------- device scratch ----------------
__device__ __align__(256) __half g_H1h[(size_t)MTOT*64];
__device__ __align__(256) __half g_H2h[(size_t)MTOT*128];
__device__ __align__(256) __half g_H3h[(size_t)MTOT*256];
__device__ __align__(256) __half g_PNh[(size_t)MTOT*512];
__device__ int   g_gvox[MTOT];
__device__ int   g_cnt[NVB];
__device__ int   g_ptr[NVB];
__device__ int   g_cur[NVB];
__device__ int   g_plist[MTOT];
__device__ int   g_bsum[SCAN_BLOCKS];
__device__ float g_W0f[64*7];
__device__ float g_B0f[64];
__device__ float g_W1f[128*64];
__device__ float g_B1f[128];
__device__ float g_W2f[256*128];
__device__ float g_B2f[256];
__device__ __align__(256) __half g_W1p[2][128*64];
__device__ __align__(256) __half g_W2h[256*128];
__device__ __align__(256) __half g_W3h[512*256];

// ---------------- helpers ----------------
__device__ __forceinline__ uint32_t smem_u32(const void* p) {
    uint32_t a;
    asm("{ .reg .u64 t; cvta.to.shared.u64 t, %1; cvt.u32.u64 %0, t; }" : "=r"(a) : "l"(p));
    return a;
}
__device__ __forceinline__ void fp16pair(float v, __half& h, __half& l) {
    h = __float2half_rn(v);
    l = __float2half_rn(v - __half2float(h));
}
__device__ __forceinline__ uint32_t packh2(float x0, float x1) {
    __half2 h = __floats2half2_rn(x0, x1);
    return *(uint32_t*)&h;
}
__device__ __forceinline__ void mma16816(float* d, const uint32_t* a, const uint32_t* b) {
    asm volatile("mma.sync.aligned.m16n8k16.row.col.f32.f16.f16.f32 "
        "{%0,%1,%2,%3}, {%4,%5,%6,%7}, {%8,%9}, {%0,%1,%2,%3};"
        : "+f"(d[0]), "+f"(d[1]), "+f"(d[2]), "+f"(d[3])
        : "r"(a[0]), "r"(a[1]), "r"(a[2]), "r"(a[3]), "r"(b[0]), "r"(b[1]));
}
__device__ __forceinline__ void ldm_x4(uint32_t& r0, uint32_t& r1, uint32_t& r2, uint32_t& r3,
                                       uint32_t addr) {
    asm volatile("ldmatrix.sync.aligned.m8n8.x4.shared.b16 {%0,%1,%2,%3}, [%4];"
        : "=r"(r0), "=r"(r1), "=r"(r2), "=r"(r3) : "r"(addr));
}
__device__ __forceinline__ void cp_async16(uint32_t dst, const void* src, uint32_t nbytes) {
    asm volatile("cp.async.cg.shared.global [%0], [%1], 16, %2;"
                 :: "r"(dst), "l"(src), "r"(nbytes));
}

// ---------------- prep kernels ----------------
__global__ void fold_kernel(const float* __restrict__ w0, const float* __restrict__ b0,
                            const float* __restrict__ w1, const float* __restrict__ b1,
                            const float* __restrict__ w2, const float* __restrict__ b2,
                            const float* __restrict__ g0, const float* __restrict__ be0,
                            const float* __restrict__ m0, const float* __restrict__ v0,
                            const float* __restrict__ g1, const float* __restrict__ be1,
                            const float* __restrict__ m1, const float* __restrict__ v1,
                            const float* __restrict__ g2, const float* __restrict__ be2,
                            const float* __restrict__ m2, const float* __restrict__ v2,
                            const float* __restrict__ g3, const float* __restrict__ be3,
                            const float* __restrict__ m3, const float* __restrict__ v3)
{
    int j = blockIdx.x * blockDim.x + threadIdx.x;
    if (j < 64) {
        float s1 = g1[j] * rsqrtf(v1[j] + BN_EPS);
        float bacc = b0[j];
        for (int i = 0; i < 7; i++) {
            float s0 = g0[i] * rsqrtf(v0[i] + BN_EPS);
            g_W0f[j*7+i] = s1 * s0 * w0[j*7+i];
            bacc += (be0[i] - m0[i]*s0) * w0[j*7+i];
        }
        g_B0f[j] = s1 * bacc + be1[j] - m1[j]*s1;
    }
    if (j < 128) {
        float s2 = g2[j] * rsqrtf(v2[j] + BN_EPS);
        for (int i = 0; i < 64; i++) g_W1f[j*64+i] = s2 * w1[j*64+i];
        g_B1f[j] = s2 * b1[j] + be2[j] - m2[j]*s2;
    }
    if (j < 256) {
        float s3 = g3[j] * rsqrtf(v3[j] + BN_EPS);
        for (int i = 0; i < 128; i++) g_W2f[j*128+i] = s3 * w2[j*128+i];
        g_B2f[j] = s3 * b2[j] + be3[j] - m3[j]*s3;
    }
}

__global__ void pairize_kernel(const float* __restrict__ w3)
{
    int i = blockIdx.x * 256 + threadIdx.x;
    __half h, l;
    if (i < 8192)               { fp16pair(g_W1f[i], h, l); g_W1p[0][i] = h; g_W1p[1][i] = l; }
    else if (i < 40960)         { int j=i-8192;  g_W2h[j] = __float2half_rn(g_W2f[j]); }
    else if (i < 40960+131072)  { int j=i-40960; g_W3h[j] = __float2half_rn(w3[j]); }
}

// ---------------- voxelize / scan / place ----------------
__global__ void voxelize_kernel(const int* __restrict__ xy)
{
    int p = blockIdx.x * blockDim.x + threadIdx.x;
    if (p >= MTOT) return;
    int b = p / NPTS;
    int gv = b * NUM_VOX + xy[2*p] * GYD + xy[2*p+1];
    g_gvox[p] = gv;
    atomicAdd(&g_cnt[gv], 1);
}
__global__ void scan_local_kernel()
{
    __shared__ int s[1024];
    int t = threadIdx.x, i = blockIdx.x * 1024 + t;
    int v = (i < NVB) ? g_cnt[i] : 0;
    s[t] = v;
    for (int off = 1; off < 1024; off <<= 1) {
        __syncthreads();
        int x = (t >= off) ? s[t - off] : 0;
        __syncthreads();
        s[t] += x;
    }
    __syncthreads();
    if (i < NVB) g_ptr[i] = s[t] - v;
    if (t == 1023) g_bsum[blockIdx.x] = s[1023];
}
__global__ void scan_bsum_kernel()
{
    __shared__ int s[512];
    int t = threadIdx.x;
    int v = (t < SCAN_BLOCKS) ? g_bsum[t] : 0;
    s[t] = v;
    for (int off = 1; off < 512; off <<= 1) {
        __syncthreads();
        int x = (t >= off) ? s[t - off] : 0;
        __syncthreads();
        s[t] += x;
    }
    __syncthreads();
    if (t < SCAN_BLOCKS) g_bsum[t] = s[t] - v;
}
__global__ void scan_add_kernel()
{
    int i = blockIdx.x * 1024 + threadIdx.x;
    if (i < NVB) { int p = g_ptr[i] + g_bsum[blockIdx.x]; g_ptr[i] = p; g_cur[i] = p; }
}
__global__ void place_kernel()
{
    int p = blockIdx.x * blockDim.x + threadIdx.x;
    if (p >= MTOT) return;
    g_plist[atomicAdd(&g_cur[g_gvox[p]], 1)] = p;
}

// ---------------- layer 0 (7 -> 64, writes fp16) ----------------
__global__ void layer0_kernel(const float* __restrict__ pt)
{
    __shared__ float ws[448];
    __shared__ float bs[64];
    int t = threadIdx.x;
    for (int i = t; i < 448; i += 256) ws[i] = g_W0f[i];
    if (t < 64) bs[t] = g_B0f[t];
    __syncthreads();
    int p = blockIdx.x * 256 + t;
    if (p >= MTOT) return;
    float x[7];
#pragma unroll
    for (int i = 0; i < 7; i++) x[i] = pt[(size_t)p*7 + i];
    uint4* oh = (uint4*)(&g_H1h[(size_t)p*64]);
#pragma unroll
    for (int g = 0; g < 8; g++) {
        uint32_t hw[4];
#pragma unroll
        for (int q = 0; q < 4; q++) {
            float y[2];
#pragma unroll
            for (int e = 0; e < 2; e++) {
                int j = g*8 + q*2 + e;
                float acc = bs[j];
#pragma unroll
                for (int i = 0; i < 7; i++) acc += x[i] * ws[j*7+i];
                y[e] = fmaxf(acc, 0.f);
            }
            hw[q] = packh2(y[0], y[1]);
        }
        oh[g] = make_uint4(hw[0],hw[1],hw[2],hw[3]);
    }
}

// ---------------- fp16 mma.sync GEMM (champion config + ldmatrix frags) ----
template<int KHALF, bool RELU, bool OUTHALF, bool SPLIT>
__global__ void __launch_bounds__(256, 2)
mma_gemm(const __half* __restrict__ A,
         const __half* __restrict__ Wh, const __half* __restrict__ Wl,
         const float* __restrict__ bias, void* __restrict__ Out, int Ntot)
{
    constexpr int KC  = KHALF / 32;
    constexpr int LDH = 40;
    constexpr int PLH = 128 * LDH;
    constexpr int NPL = SPLIT ? 3 : 2;
    constexpr int STG = NPL * PLH;
    extern __shared__ __half sm[];
    __shared__ float bias_s[128];

    const int tid = threadIdx.x, wid = tid >> 5, lane = tid & 31;
    const int g = lane >> 2, t4 = lane & 3;
    const int wm = wid & 1, wn = wid >> 1;
    const int nt = blockIdx.x, bm = blockIdx.y * 128;

    if (tid < 128) bias_s[tid] = bias[nt*128 + tid];

    const int q = lane & 7, h = lane >> 3;
    const uint32_t al  = (uint32_t)(((((h&1)*8 + q)*LDH) + (h>>1)*8) * 2);
    const uint32_t blo = (uint32_t)(((((h>>1)*8 + q)*LDH) + (h&1)*8) * 2);
    const uint32_t sbase = smem_u32(sm);

    auto issue = [&](int c) {
        __half* dst0 = sm + (c % 3) * STG;
        for (int i = tid; i < NPL*512; i += 256) {
            int pl = i >> 9, j = i & 511, row = j >> 2, seg = j & 3;
            uint32_t dst = smem_u32(dst0 + pl*PLH + row*LDH) + seg*16;
            const __half* base = (pl==0) ? A : (pl==1) ? Wh : Wl;
            int rg = (pl == 0) ? (bm + row) : (nt*128 + row);
            const __half* src = base + (size_t)rg*KHALF + c*32 + seg*8;
            uint32_t n = (pl != 0 || (bm + row) < MTOT) ? 16u : 0u;
            cp_async16(dst, src, n);
        }
        asm volatile("cp.async.commit_group;");
    };

    float acc[4][4][4];
#pragma unroll
    for (int i = 0; i < 4; i++)
#pragma unroll
        for (int j = 0; j < 4; j++)
#pragma unroll
            for (int p = 0; p < 4; p++) acc[i][j][p] = 0.f;

    issue(0);
    if (KC > 1) issue(1);
    for (int c = 0; c < KC; c++) {
        if (c <= KC - 2) asm volatile("cp.async.wait_group 1;");
        else             asm volatile("cp.async.wait_group 0;");
        __syncthreads();
        if (c + 2 < KC) issue(c + 2);
        const uint32_t stg = sbase + (uint32_t)((c % 3) * STG * 2);
        const uint32_t ab  = stg + (uint32_t)(wm*64*LDH*2) + al;
        const uint32_t bhb = stg + (uint32_t)(PLH*2) + (uint32_t)(wn*32*LDH*2) + blo;
        const uint32_t blb = bhb + (uint32_t)(PLH*2);
#pragma unroll
        for (int ks = 0; ks < 32; ks += 16) {
            uint32_t af[4][4], bh[4][2];
#pragma unroll
            for (int mt = 0; mt < 4; mt++)
                ldm_x4(af[mt][0], af[mt][1], af[mt][2], af[mt][3],
                       ab + (uint32_t)((mt*16*LDH + ks) * 2));
#pragma unroll
            for (int np = 0; np < 2; np++)
                ldm_x4(bh[2*np][0], bh[2*np][1], bh[2*np+1][0], bh[2*np+1][1],
                       bhb + (uint32_t)((np*16*LDH + ks) * 2));
#pragma unroll
            for (int mt = 0; mt < 4; mt++)
#pragma unroll
                for (int nb = 0; nb < 4; nb++) mma16816(acc[mt][nb], af[mt], bh[nb]);
            if (SPLIT) {
                uint32_t bl[4][2];
#pragma unroll
                for (int np = 0; np < 2; np++)
                    ldm_x4(bl[2*np][0], bl[2*np][1], bl[2*np+1][0], bl[2*np+1][1],
                           blb + (uint32_t)((np*16*LDH + ks) * 2));
#pragma unroll
                for (int mt = 0; mt < 4; mt++)
#pragma unroll
                    for (int nb = 0; nb < 4; nb++) mma16816(acc[mt][nb], af[mt], bl[nb]);
            }
        }
    }

    // epilogue
#pragma unroll
    for (int mt = 0; mt < 4; mt++) {
#pragma unroll
        for (int nb = 0; nb < 4; nb++) {
            int col = wn*32 + nb*8 + t4*2;
            float bv0 = bias_s[col], bv1 = bias_s[col + 1];
#pragma unroll
            for (int hh = 0; hh < 2; hh++) {
                int r = bm + wm*64 + mt*16 + g + hh*8;
                if (r >= MTOT) continue;
                float x0 = acc[mt][nb][2*hh]   + bv0;
                float x1 = acc[mt][nb][2*hh+1] + bv1;
                if (RELU) { x0 = fmaxf(x0, 0.f); x1 = fmaxf(x1, 0.f); }
                if (OUTHALF) {
                    uint32_t* o = (uint32_t*)Out;
                    o[((size_t)r*Ntot + nt*128 + col) >> 1] = packh2(x0, x1);
                } else {
                    *(float2*)((float*)Out + (size_t)r*Ntot + nt*128 + col) = make_float2(x0, x1);
                }
            }
        }
    }
}

// ---------------- compression: 2 voxels per warp, shared wc loads ----------
__global__ void comp_kernel(const float* __restrict__ wc, const float* __restrict__ bc,
                            float* __restrict__ out)
{
    const int lane = threadIdx.x & 31;
    const int warp = (blockIdx.x * blockDim.x + threadIdx.x) >> 5;
    const int nwarps = (gridDim.x * blockDim.x) >> 5;
    const float4* wc4 = (const float4*)wc;
    const int npairs = (NVB + 1) >> 1;

    for (int pr = warp; pr < npairs; pr += nwarps) {
        int gv0 = pr * 2;
        int gv1 = gv0 + 1;
        int c0 = g_cnt[gv0];
        int c1 = (gv1 < NVB) ? g_cnt[gv1] : 0;
        if ((c0 | c1) == 0) continue;

        float4 mv0[4], mv1[4];
#pragma unroll
        for (int t = 0; t < 4; t++) {
            mv0[t] = make_float4(0.f, 0.f, 0.f, 0.f);
            mv1[t] = make_float4(0.f, 0.f, 0.f, 0.f);
        }
        if (c0) {
#pragma unroll
            for (int t = 0; t < 4; t++) mv0[t] = make_float4(-FLT_MAX,-FLT_MAX,-FLT_MAX,-FLT_MAX);
            int base = g_ptr[gv0];
            for (int pi = 0; pi < c0; pi++) {
                int p = g_plist[base + pi];
                const uint2* pn2 = (const uint2*)(g_PNh + (size_t)p * 512);
#pragma unroll
                for (int t = 0; t < 4; t++) {
                    uint2 u = pn2[t*32 + lane];
                    float2 f0 = __half22float2(*(const __half2*)&u.x);
                    float2 f1 = __half22float2(*(const __half2*)&u.y);
                    mv0[t].x = fmaxf(mv0[t].x, f0.x); mv0[t].y = fmaxf(mv0[t].y, f0.y);
                    mv0[t].z = fmaxf(mv0[t].z, f1.x); mv0[t].w = fmaxf(mv0[t].w, f1.y);
                }
            }
        }
        if (c1) {
#pragma unroll
            for (int t = 0; t < 4; t++) mv1[t] = make_float4(-FLT_MAX,-FLT_MAX,-FLT_MAX,-FLT_MAX);
            int base = g_ptr[gv1];
            for (int pi = 0; pi < c1; pi++) {
                int p = g_plist[base + pi];
                const uint2* pn2 = (const uint2*)(g_PNh + (size_t)p * 512);
#pragma unroll
                for (int t = 0; t < 4; t++) {
                    uint2 u = pn2[t*32 + lane];
                    float2 f0 = __half22float2(*(const __half2*)&u.x);
                    float2 f1 = __half22float2(*(const __half2*)&u.y);
                    mv1[t].x = fmaxf(mv1[t].x, f0.x); mv1[t].y = fmaxf(mv1[t].y, f0.y);
                    mv1[t].z = fmaxf(mv1[t].z, f1.x); mv1[t].w = fmaxf(mv1[t].w, f1.y);
                }
            }
        }

        float acc0[32], acc1[32];
#pragma unroll
        for (int c = 0; c < 32; c++) { acc0[c] = 0.f; acc1[c] = 0.f; }
#pragma unroll
        for (int t = 0; t < 4; t++)
#pragma unroll
            for (int c = 0; c < 32; c++) {
                float4 w = __ldg(&wc4[c*128 + t*32 + lane]);
                acc0[c] += mv0[t].x*w.x + mv0[t].y*w.y + mv0[t].z*w.z + mv0[t].w*w.w;
                acc1[c] += mv1[t].x*w.x + mv1[t].y*w.y + mv1[t].z*w.z + mv1[t].w*w.w;
            }

#pragma unroll
        for (int step = 0; step < 5; step++) {
            const int off = 16 >> step, half = 16 >> step;
            bool up = (lane & off) != 0;
#pragma unroll
            for (int i = 0; i < 16; i++) if (i < half) {
                float g0 = up ? acc0[i] : acc0[i + half];
                float k0 = up ? acc0[i + half] : acc0[i];
                acc0[i] = k0 + __shfl_xor_sync(0xffffffffu, g0, off);
                float g1 = up ? acc1[i] : acc1[i + half];
                float k1 = up ? acc1[i + half] : acc1[i];
                acc1[i] = k1 + __shfl_xor_sync(0xffffffffu, g1, off);
            }
        }

        if (c0) {
            int b = gv0 / NUM_VOX, v = gv0 - b * NUM_VOX;
            out[(size_t)(b*32 + lane) * NUM_VOX + v] = fmaxf(acc0[0] + bc[lane], 0.f);
        }
        if (c1) {
            int b = gv1 / NUM_VOX, v = gv1 - b * NUM_VOX;
            out[(size_t)(b*32 + lane) * NUM_VOX + v] = fmaxf(acc1[0] + bc[lane], 0.f);
        }
    }
}

// ---------------- host launch ----------------
extern "C" void kernel_launch(void* const* d_in, const int* in_sizes, int n_in,
                              void* d_out, int out_size)
{
    const float* pt  = (const float*)d_in[0];
    const int*   xy  = (const int*)  d_in[1];
    const float* w0  = (const float*)d_in[2];  const float* b0 = (const float*)d_in[3];
    const float* w1  = (const float*)d_in[4];  const float* b1 = (const float*)d_in[5];
    const float* w2  = (const float*)d_in[6];  const float* b2 = (const float*)d_in[7];
    const float* w3  = (const float*)d_in[8];  const float* b3 = (const float*)d_in[9];
    const float* g0  = (const float*)d_in[10]; const float* be0 = (const float*)d_in[11];
    const float* m0  = (const float*)d_in[12]; const float* v0  = (const float*)d_in[13];
    const float* g1  = (const float*)d_in[14]; const float* be1 = (const float*)d_in[15];
    const float* m1  = (const float*)d_in[16]; const float* v1  = (const float*)d_in[17];
    const float* g2  = (const float*)d_in[18]; const float* be2 = (const float*)d_in[19];
    const float* m2  = (const float*)d_in[20]; const float* v2  = (const float*)d_in[21];
    const float* g3  = (const float*)d_in[22]; const float* be3 = (const float*)d_in[23];
    const float* m3  = (const float*)d_in[24]; const float* v3  = (const float*)d_in[25];
    const float* wc  = (const float*)d_in[26]; const float* bc  = (const float*)d_in[27];
    float* out = (float*)d_out;

    constexpr int DSMEM_S = 3 * 3 * 128 * 40 * 2;   // 92160 B (split)
    constexpr int DSMEM_N = 3 * 2 * 128 * 40 * 2;   // 61440 B
    static void *cnt_a = nullptr, *H1_a, *H2_a, *H3_a, *PN_a;
    static void *W1p_a, *W2h_a, *W3h_a, *B1f_a, *B2f_a;
    static cudaStream_t s2;
    static cudaEvent_t evFork, evJoin;
    if (!cnt_a) {
        cudaGetSymbolAddress(&cnt_a, g_cnt);
        cudaGetSymbolAddress(&H1_a, g_H1h);  cudaGetSymbolAddress(&H2_a, g_H2h);
        cudaGetSymbolAddress(&H3_a, g_H3h);  cudaGetSymbolAddress(&PN_a, g_PNh);
        cudaGetSymbolAddress(&W1p_a, g_W1p); cudaGetSymbolAddress(&W2h_a, g_W2h);
        cudaGetSymbolAddress(&W3h_a, g_W3h);
        cudaGetSymbolAddress(&B1f_a, g_B1f); cudaGetSymbolAddress(&B2f_a, g_B2f);
        cudaFuncSetAttribute(mma_gemm< 64, true,  true,  true >, cudaFuncAttributeMaxDynamicSharedMemorySize, DSMEM_S);
        cudaFuncSetAttribute(mma_gemm<128, true,  true,  false>, cudaFuncAttributeMaxDynamicSharedMemorySize, DSMEM_N);
        cudaFuncSetAttribute(mma_gemm<256, false, true,  false>, cudaFuncAttributeMaxDynamicSharedMemorySize, DSMEM_N);
        cudaStreamCreateWithFlags(&s2, cudaStreamNonBlocking);
        cudaEventCreateWithFlags(&evFork, cudaEventDisableTiming);
        cudaEventCreateWithFlags(&evJoin, cudaEventDisableTiming);
    }

    const __half* H1 = (const __half*)H1_a;
    const __half* H2 = (const __half*)H2_a;
    const __half* H3 = (const __half*)H3_a;
    const __half* W1 = (const __half*)W1p_a;
    const __half* W2 = (const __half*)W2h_a;
    const __half* W3 = (const __half*)W3h_a;

    // ---- fork: voxel pipeline on s2, overlapped with MLP chain ----
    cudaEventRecord(evFork, 0);
    cudaStreamWaitEvent(s2, evFork, 0);
    cudaMemsetAsync(cnt_a, 0, NVB * sizeof(int), s2);
    cudaMemsetAsync(d_out, 0, (size_t)out_size * sizeof(float), s2);
    voxelize_kernel<<<(MTOT+255)/256, 256, 0, s2>>>(xy);
    scan_local_kernel<<<SCAN_BLOCKS, 1024, 0, s2>>>();
    scan_bsum_kernel<<<1, 512, 0, s2>>>();
    scan_add_kernel<<<SCAN_BLOCKS, 1024, 0, s2>>>();
    place_kernel<<<(MTOT+255)/256, 256, 0, s2>>>();
    cudaEventRecord(evJoin, s2);

    // ---- MLP chain ----
    fold_kernel<<<1, 256>>>(w0,b0,w1,b1,w2,b2, g0,be0,m0,v0, g1,be1,m1,v1,
                            g2,be2,m2,v2, g3,be3,m3,v3);
    pairize_kernel<<<672, 256>>>(w3);
    layer0_kernel<<<(MTOT+255)/256, 256>>>(pt);
    mma_gemm< 64, true,  true,  true ><<<dim3(1, MTILES), 256, DSMEM_S>>>(
        H1, W1, W1 + 128*64,  (const float*)B1f_a, (void*)H2_a, 128);
    mma_gemm<128, true,  true,  false><<<dim3(2, MTILES), 256, DSMEM_N>>>(
        H2, W2, W2, (const float*)B2f_a, (void*)H3_a, 256);
    mma_gemm<256, false, true,  false><<<dim3(4, MTILES), 256, DSMEM_N>>>(
        H3, W3, W3, b3, (void*)PN_a, 512);

    // ---- join, then compression ----
    cudaStreamWaitEvent(0, evJoin, 0);
    comp_kernel<<<2048, 256>>>(wc, bc, out);
}

// round 16
// speedup vs baseline: 1.0893x; 1.0893x over previous
#include <cuda_runtime.h>
#include <cuda_fp16.h>
#include <cstdint>
#include <cfloat>

#define GXD 480
#define GYD 360
#define NUM_VOX (GXD*GYD)
#define BATCH 2
#define NPTS 100000
#define MTOT (BATCH*NPTS)
#define NVB (BATCH*NUM_VOX)
#define BN_EPS 1e-5f
#define SCAN_BLOCKS 338
#define MTILES ((MTOT+127)/128)   /* 1563 */

// ---------------- device scratch ----------------
__device__ __align__(256) __half g_H1h[(size_t)MTOT*64];
__device__ __align__(256) __half g_H2h[(size_t)MTOT*128];
__device__ __align__(256) __half g_H3h[(size_t)MTOT*256];
__device__ __align__(256) __half g_PNh[(size_t)MTOT*512];
__device__ int   g_gvox[MTOT];
__device__ int   g_cnt[NVB];
__device__ int   g_ptr[NVB];
__device__ int   g_cur[NVB];
__device__ int   g_plist[MTOT];
__device__ int   g_bsum[SCAN_BLOCKS];
__device__ float g_W0f[64*7];
__device__ float g_B0f[64];
__device__ float g_W1f[128*64];
__device__ float g_B1f[128];
__device__ float g_W2f[256*128];
__device__ float g_B2f[256];
__device__ __align__(256) __half g_W1h[128*64];
__device__ __align__(256) __half g_W2h[256*128];
__device__ __align__(256) __half g_W3h[512*256];

// ---------------- helpers ----------------
__device__ __forceinline__ uint32_t smem_u32(const void* p) {
    uint32_t a;
    asm("{ .reg .u64 t; cvta.to.shared.u64 t, %1; cvt.u32.u64 %0, t; }" : "=r"(a) : "l"(p));
    return a;
}
__device__ __forceinline__ uint32_t packh2(float x0, float x1) {
    __half2 h = __floats2half2_rn(x0, x1);
    return *(uint32_t*)&h;
}
__device__ __forceinline__ void mma16816(float* d, const uint32_t* a, const uint32_t* b) {
    asm volatile("mma.sync.aligned.m16n8k16.row.col.f32.f16.f16.f32 "
        "{%0,%1,%2,%3}, {%4,%5,%6,%7}, {%8,%9}, {%0,%1,%2,%3};"
        : "+f"(d[0]), "+f"(d[1]), "+f"(d[2]), "+f"(d[3])
        : "r"(a[0]), "r"(a[1]), "r"(a[2]), "r"(a[3]), "r"(b[0]), "r"(b[1]));
}
__device__ __forceinline__ void ldm_x4(uint32_t& r0, uint32_t& r1, uint32_t& r2, uint32_t& r3,
                                       uint32_t addr) {
    asm volatile("ldmatrix.sync.aligned.m8n8.x4.shared.b16 {%0,%1,%2,%3}, [%4];"
        : "=r"(r0), "=r"(r1), "=r"(r2), "=r"(r3) : "r"(addr));
}
__device__ __forceinline__ void cp_async16(uint32_t dst, const void* src, uint32_t nbytes) {
    asm volatile("cp.async.cg.shared.global [%0], [%1], 16, %2;"
                 :: "r"(dst), "l"(src), "r"(nbytes));
}

// ---------------- prep kernels ----------------
__global__ void fold_kernel(const float* __restrict__ w0, const float* __restrict__ b0,
                            const float* __restrict__ w1, const float* __restrict__ b1,
                            const float* __restrict__ w2, const float* __restrict__ b2,
                            const float* __restrict__ g0, const float* __restrict__ be0,
                            const float* __restrict__ m0, const float* __restrict__ v0,
                            const float* __restrict__ g1, const float* __restrict__ be1,
                            const float* __restrict__ m1, const float* __restrict__ v1,
                            const float* __restrict__ g2, const float* __restrict__ be2,
                            const float* __restrict__ m2, const float* __restrict__ v2,
                            const float* __restrict__ g3, const float* __restrict__ be3,
                            const float* __restrict__ m3, const float* __restrict__ v3)
{
    int j = blockIdx.x * blockDim.x + threadIdx.x;
    if (j < 64) {
        float s1 = g1[j] * rsqrtf(v1[j] + BN_EPS);
        float bacc = b0[j];
        for (int i = 0; i < 7; i++) {
            float s0 = g0[i] * rsqrtf(v0[i] + BN_EPS);
            g_W0f[j*7+i] = s1 * s0 * w0[j*7+i];
            bacc += (be0[i] - m0[i]*s0) * w0[j*7+i];
        }
        g_B0f[j] = s1 * bacc + be1[j] - m1[j]*s1;
    }
    if (j < 128) {
        float s2 = g2[j] * rsqrtf(v2[j] + BN_EPS);
        for (int i = 0; i < 64; i++) g_W1f[j*64+i] = s2 * w1[j*64+i];
        g_B1f[j] = s2 * b1[j] + be2[j] - m2[j]*s2;
    }
    if (j < 256) {
        float s3 = g3[j] * rsqrtf(v3[j] + BN_EPS);
        for (int i = 0; i < 128; i++) g_W2f[j*128+i] = s3 * w2[j*128+i];
        g_B2f[j] = s3 * b2[j] + be3[j] - m3[j]*s3;
    }
}

__global__ void pairize_kernel(const float* __restrict__ w3)
{
    int i = blockIdx.x * 256 + threadIdx.x;
    if (i < 8192)               { g_W1h[i] = __float2half_rn(g_W1f[i]); }
    else if (i < 40960)         { int j=i-8192;  g_W2h[j] = __float2half_rn(g_W2f[j]); }
    else if (i < 40960+131072)  { int j=i-40960; g_W3h[j] = __float2half_rn(w3[j]); }
}

// ---------------- voxelize / scan / place ----------------
__global__ void voxelize_kernel(const int* __restrict__ xy)
{
    int p = blockIdx.x * blockDim.x + threadIdx.x;
    if (p >= MTOT) return;
    int b = p / NPTS;
    int gv = b * NUM_VOX + xy[2*p] * GYD + xy[2*p+1];
    g_gvox[p] = gv;
    atomicAdd(&g_cnt[gv], 1);
}
__global__ void scan_local_kernel()
{
    __shared__ int s[1024];
    int t = threadIdx.x, i = blockIdx.x * 1024 + t;
    int v = (i < NVB) ? g_cnt[i] : 0;
    s[t] = v;
    for (int off = 1; off < 1024; off <<= 1) {
        __syncthreads();
        int x = (t >= off) ? s[t - off] : 0;
        __syncthreads();
        s[t] += x;
    }
    __syncthreads();
    if (i < NVB) g_ptr[i] = s[t] - v;
    if (t == 1023) g_bsum[blockIdx.x] = s[1023];
}
__global__ void scan_bsum_kernel()
{
    __shared__ int s[512];
    int t = threadIdx.x;
    int v = (t < SCAN_BLOCKS) ? g_bsum[t] : 0;
    s[t] = v;
    for (int off = 1; off < 512; off <<= 1) {
        __syncthreads();
        int x = (t >= off) ? s[t - off] : 0;
        __syncthreads();
        s[t] += x;
    }
    __syncthreads();
    if (t < SCAN_BLOCKS) g_bsum[t] = s[t] - v;
}
__global__ void scan_add_kernel()
{
    int i = blockIdx.x * 1024 + threadIdx.x;
    if (i < NVB) { int p = g_ptr[i] + g_bsum[blockIdx.x]; g_ptr[i] = p; g_cur[i] = p; }
}
__global__ void place_kernel()
{
    int p = blockIdx.x * blockDim.x + threadIdx.x;
    if (p >= MTOT) return;
    g_plist[atomicAdd(&g_cur[g_gvox[p]], 1)] = p;
}

// ---------------- layer 0 (7 -> 64, writes fp16) ----------------
__global__ void layer0_kernel(const float* __restrict__ pt)
{
    __shared__ float ws[448];
    __shared__ float bs[64];
    int t = threadIdx.x;
    for (int i = t; i < 448; i += 256) ws[i] = g_W0f[i];
    if (t < 64) bs[t] = g_B0f[t];
    __syncthreads();
    int p = blockIdx.x * 256 + t;
    if (p >= MTOT) return;
    float x[7];
#pragma unroll
    for (int i = 0; i < 7; i++) x[i] = pt[(size_t)p*7 + i];
    uint4* oh = (uint4*)(&g_H1h[(size_t)p*64]);
#pragma unroll
    for (int g = 0; g < 8; g++) {
        uint32_t hw[4];
#pragma unroll
        for (int q = 0; q < 4; q++) {
            float y[2];
#pragma unroll
            for (int e = 0; e < 2; e++) {
                int j = g*8 + q*2 + e;
                float acc = bs[j];
#pragma unroll
                for (int i = 0; i < 7; i++) acc += x[i] * ws[j*7+i];
                y[e] = fmaxf(acc, 0.f);
            }
            hw[q] = packh2(y[0], y[1]);
        }
        oh[g] = make_uint4(hw[0],hw[1],hw[2],hw[3]);
    }
}

// ---------------- fp16 mma.sync GEMM (champion config + ldmatrix frags) ----
template<int KHALF, bool RELU, bool OUTHALF, bool SPLIT>
__global__ void __launch_bounds__(256, 2)
mma_gemm(const __half* __restrict__ A,
         const __half* __restrict__ Wh, const __half* __restrict__ Wl,
         const float* __restrict__ bias, void* __restrict__ Out, int Ntot)
{
    constexpr int KC  = KHALF / 32;
    constexpr int LDH = 40;
    constexpr int PLH = 128 * LDH;
    constexpr int NPL = SPLIT ? 3 : 2;
    constexpr int STG = NPL * PLH;
    extern __shared__ __half sm[];
    __shared__ float bias_s[128];

    const int tid = threadIdx.x, wid = tid >> 5, lane = tid & 31;
    const int g = lane >> 2, t4 = lane & 3;
    const int wm = wid & 1, wn = wid >> 1;
    const int nt = blockIdx.x, bm = blockIdx.y * 128;

    if (tid < 128) bias_s[tid] = bias[nt*128 + tid];

    const int q = lane & 7, h = lane >> 3;
    const uint32_t al  = (uint32_t)(((((h&1)*8 + q)*LDH) + (h>>1)*8) * 2);
    const uint32_t blo = (uint32_t)(((((h>>1)*8 + q)*LDH) + (h&1)*8) * 2);
    const uint32_t sbase = smem_u32(sm);

    auto issue = [&](int c) {
        __half* dst0 = sm + (c % 3) * STG;
        for (int i = tid; i < NPL*512; i += 256) {
            int pl = i >> 9, j = i & 511, row = j >> 2, seg = j & 3;
            uint32_t dst = smem_u32(dst0 + pl*PLH + row*LDH) + seg*16;
            const __half* base = (pl==0) ? A : (pl==1) ? Wh : Wl;
            int rg = (pl == 0) ? (bm + row) : (nt*128 + row);
            const __half* src = base + (size_t)rg*KHALF + c*32 + seg*8;
            uint32_t n = (pl != 0 || (bm + row) < MTOT) ? 16u : 0u;
            cp_async16(dst, src, n);
        }
        asm volatile("cp.async.commit_group;");
    };

    float acc[4][4][4];
#pragma unroll
    for (int i = 0; i < 4; i++)
#pragma unroll
        for (int j = 0; j < 4; j++)
#pragma unroll
            for (int p = 0; p < 4; p++) acc[i][j][p] = 0.f;

    issue(0);
    if (KC > 1) issue(1);
    for (int c = 0; c < KC; c++) {
        if (c <= KC - 2) asm volatile("cp.async.wait_group 1;");
        else             asm volatile("cp.async.wait_group 0;");
        __syncthreads();
        if (c + 2 < KC) issue(c + 2);
        const uint32_t stg = sbase + (uint32_t)((c % 3) * STG * 2);
        const uint32_t ab  = stg + (uint32_t)(wm*64*LDH*2) + al;
        const uint32_t bhb = stg + (uint32_t)(PLH*2) + (uint32_t)(wn*32*LDH*2) + blo;
        const uint32_t blb = bhb + (uint32_t)(PLH*2);
#pragma unroll
        for (int ks = 0; ks < 32; ks += 16) {
            uint32_t af[4][4], bh[4][2];
#pragma unroll
            for (int mt = 0; mt < 4; mt++)
                ldm_x4(af[mt][0], af[mt][1], af[mt][2], af[mt][3],
                       ab + (uint32_t)((mt*16*LDH + ks) * 2));
#pragma unroll
            for (int np = 0; np < 2; np++)
                ldm_x4(bh[2*np][0], bh[2*np][1], bh[2*np+1][0], bh[2*np+1][1],
                       bhb + (uint32_t)((np*16*LDH + ks) * 2));
#pragma unroll
            for (int mt = 0; mt < 4; mt++)
#pragma unroll
                for (int nb = 0; nb < 4; nb++) mma16816(acc[mt][nb], af[mt], bh[nb]);
            if (SPLIT) {
                uint32_t bl[4][2];
#pragma unroll
                for (int np = 0; np < 2; np++)
                    ldm_x4(bl[2*np][0], bl[2*np][1], bl[2*np+1][0], bl[2*np+1][1],
                           blb + (uint32_t)((np*16*LDH + ks) * 2));
#pragma unroll
                for (int mt = 0; mt < 4; mt++)
#pragma unroll
                    for (int nb = 0; nb < 4; nb++) mma16816(acc[mt][nb], af[mt], bl[nb]);
            }
        }
    }

    // epilogue
#pragma unroll
    for (int mt = 0; mt < 4; mt++) {
#pragma unroll
        for (int nb = 0; nb < 4; nb++) {
            int col = wn*32 + nb*8 + t4*2;
            float bv0 = bias_s[col], bv1 = bias_s[col + 1];
#pragma unroll
            for (int hh = 0; hh < 2; hh++) {
                int r = bm + wm*64 + mt*16 + g + hh*8;
                if (r >= MTOT) continue;
                float x0 = acc[mt][nb][2*hh]   + bv0;
                float x1 = acc[mt][nb][2*hh+1] + bv1;
                if (RELU) { x0 = fmaxf(x0, 0.f); x1 = fmaxf(x1, 0.f); }
                if (OUTHALF) {
                    uint32_t* o = (uint32_t*)Out;
                    o[((size_t)r*Ntot + nt*128 + col) >> 1] = packh2(x0, x1);
                } else {
                    *(float2*)((float*)Out + (size_t)r*Ntot + nt*128 + col) = make_float2(x0, x1);
                }
            }
        }
    }
}

// ---------------- compression (R14 champion version) ----------------
__global__ void comp_kernel(const float* __restrict__ wc, const float* __restrict__ bc,
                            float* __restrict__ out)
{
    const int lane = threadIdx.x & 31;
    const int warp = (blockIdx.x * blockDim.x + threadIdx.x) >> 5;
    const int nwarps = (gridDim.x * blockDim.x) >> 5;
    const float4* wc4 = (const float4*)wc;
    for (int gv = warp; gv < NVB; gv += nwarps) {
        int c_ = g_cnt[gv];
        if (c_ == 0) continue;
        int base = g_ptr[gv];
        float4 mv[4];
#pragma unroll
        for (int t = 0; t < 4; t++) mv[t] = make_float4(-FLT_MAX,-FLT_MAX,-FLT_MAX,-FLT_MAX);
        for (int pi = 0; pi < c_; pi++) {
            int p = g_plist[base + pi];
            const uint2* pn2 = (const uint2*)(g_PNh + (size_t)p * 512);
#pragma unroll
            for (int t = 0; t < 4; t++) {
                uint2 u = pn2[t*32 + lane];
                float2 f0 = __half22float2(*(const __half2*)&u.x);
                float2 f1 = __half22float2(*(const __half2*)&u.y);
                mv[t].x = fmaxf(mv[t].x, f0.x); mv[t].y = fmaxf(mv[t].y, f0.y);
                mv[t].z = fmaxf(mv[t].z, f1.x); mv[t].w = fmaxf(mv[t].w, f1.y);
            }
        }
        float acc[32];
#pragma unroll
        for (int c = 0; c < 32; c++) acc[c] = 0.f;
#pragma unroll
        for (int t = 0; t < 4; t++)
#pragma unroll
            for (int c = 0; c < 32; c++) {
                float4 w = __ldg(&wc4[c*128 + t*32 + lane]);
                acc[c] += mv[t].x*w.x + mv[t].y*w.y + mv[t].z*w.z + mv[t].w*w.w;
            }
#pragma unroll
        for (int step = 0; step < 5; step++) {
            const int off = 16 >> step, half = 16 >> step;
            bool up = (lane & off) != 0;
#pragma unroll
            for (int i = 0; i < 16; i++) if (i < half) {
                float give = up ? acc[i] : acc[i + half];
                float keep = up ? acc[i + half] : acc[i];
                acc[i] = keep + __shfl_xor_sync(0xffffffffu, give, off);
            }
        }
        int b = gv / NUM_VOX, v = gv - b * NUM_VOX;
        out[(size_t)(b*32 + lane) * NUM_VOX + v] = fmaxf(acc[0] + bc[lane], 0.f);
    }
}

// ---------------- host launch ----------------
extern "C" void kernel_launch(void* const* d_in, const int* in_sizes, int n_in,
                              void* d_out, int out_size)
{
    const float* pt  = (const float*)d_in[0];
    const int*   xy  = (const int*)  d_in[1];
    const float* w0  = (const float*)d_in[2];  const float* b0 = (const float*)d_in[3];
    const float* w1  = (const float*)d_in[4];  const float* b1 = (const float*)d_in[5];
    const float* w2  = (const float*)d_in[6];  const float* b2 = (const float*)d_in[7];
    const float* w3  = (const float*)d_in[8];  const float* b3 = (const float*)d_in[9];
    const float* g0  = (const float*)d_in[10]; const float* be0 = (const float*)d_in[11];
    const float* m0  = (const float*)d_in[12]; const float* v0  = (const float*)d_in[13];
    const float* g1  = (const float*)d_in[14]; const float* be1 = (const float*)d_in[15];
    const float* m1  = (const float*)d_in[16]; const float* v1  = (const float*)d_in[17];
    const float* g2  = (const float*)d_in[18]; const float* be2 = (const float*)d_in[19];
    const float* m2  = (const float*)d_in[20]; const float* v2  = (const float*)d_in[21];
    const float* g3  = (const float*)d_in[22]; const float* be3 = (const float*)d_in[23];
    const float* m3  = (const float*)d_in[24]; const float* v3  = (const float*)d_in[25];
    const float* wc  = (const float*)d_in[26]; const float* bc  = (const float*)d_in[27];
    float* out = (float*)d_out;

    constexpr int DSMEM_N = 3 * 2 * 128 * 40 * 2;   // 61440 B (A + Wh)
    static void *cnt_a = nullptr, *H1_a, *H2_a, *H3_a, *PN_a;
    static void *W1h_a, *W2h_a, *W3h_a, *B1f_a, *B2f_a;
    static cudaStream_t s2;
    static cudaEvent_t evFork, evJoin;
    if (!cnt_a) {
        cudaGetSymbolAddress(&cnt_a, g_cnt);
        cudaGetSymbolAddress(&H1_a, g_H1h);  cudaGetSymbolAddress(&H2_a, g_H2h);
        cudaGetSymbolAddress(&H3_a, g_H3h);  cudaGetSymbolAddress(&PN_a, g_PNh);
        cudaGetSymbolAddress(&W1h_a, g_W1h); cudaGetSymbolAddress(&W2h_a, g_W2h);
        cudaGetSymbolAddress(&W3h_a, g_W3h);
        cudaGetSymbolAddress(&B1f_a, g_B1f); cudaGetSymbolAddress(&B2f_a, g_B2f);
        cudaFuncSetAttribute(mma_gemm< 64, true,  true,  false>, cudaFuncAttributeMaxDynamicSharedMemorySize, DSMEM_N);
        cudaFuncSetAttribute(mma_gemm<128, true,  true,  false>, cudaFuncAttributeMaxDynamicSharedMemorySize, DSMEM_N);
        cudaFuncSetAttribute(mma_gemm<256, false, true,  false>, cudaFuncAttributeMaxDynamicSharedMemorySize, DSMEM_N);
        cudaStreamCreateWithFlags(&s2, cudaStreamNonBlocking);
        cudaEventCreateWithFlags(&evFork, cudaEventDisableTiming);
        cudaEventCreateWithFlags(&evJoin, cudaEventDisableTiming);
    }

    const __half* H1 = (const __half*)H1_a;
    const __half* H2 = (const __half*)H2_a;
    const __half* H3 = (const __half*)H3_a;
    const __half* W1 = (const __half*)W1h_a;
    const __half* W2 = (const __half*)W2h_a;
    const __half* W3 = (const __half*)W3h_a;

    // ---- fork: voxel pipeline on s2, overlapped with MLP chain ----
    cudaEventRecord(evFork, 0);
    cudaStreamWaitEvent(s2, evFork, 0);
    cudaMemsetAsync(cnt_a, 0, NVB * sizeof(int), s2);
    cudaMemsetAsync(d_out, 0, (size_t)out_size * sizeof(float), s2);
    voxelize_kernel<<<(MTOT+255)/256, 256, 0, s2>>>(xy);
    scan_local_kernel<<<SCAN_BLOCKS, 1024, 0, s2>>>();
    scan_bsum_kernel<<<1, 512, 0, s2>>>();
    scan_add_kernel<<<SCAN_BLOCKS, 1024, 0, s2>>>();
    place_kernel<<<(MTOT+255)/256, 256, 0, s2>>>();
    cudaEventRecord(evJoin, s2);

    // ---- MLP chain ----
    fold_kernel<<<1, 256>>>(w0,b0,w1,b1,w2,b2, g0,be0,m0,v0, g1,be1,m1,v1,
                            g2,be2,m2,v2, g3,be3,m3,v3);
    pairize_kernel<<<672, 256>>>(w3);
    layer0_kernel<<<(MTOT+255)/256, 256>>>(pt);
    mma_gemm< 64, true,  true,  false><<<dim3(1, MTILES), 256, DSMEM_N>>>(
        H1, W1, W1, (const float*)B1f_a, (void*)H2_a, 128);
    mma_gemm<128, true,  true,  false><<<dim3(2, MTILES), 256, DSMEM_N>>>(
        H2, W2, W2, (const float*)B2f_a, (void*)H3_a, 256);
    mma_gemm<256, false, true,  false><<<dim3(4, MTILES), 256, DSMEM_N>>>(
        H3, W3, W3, b3, (void*)PN_a, 512);

    // ---- join, then compression ----
    cudaStreamWaitEvent(0, evJoin, 0);
    comp_kernel<<<2048, 256>>>(wc, bc, out);
}